// round 7
// baseline (speedup 1.0000x reference)
#include <cuda_runtime.h>
#include <math.h>

#define DGRID 200
#define NCELL 8000000
#define AT 4            /* a-layers per block */
#define BT 5            /* b rows per block */
#define CW 204          /* padded row width: c in [-2, 201] */
#define SAH (AT + 4)    /* 8 halo a-layers */
#define SBH (BT + 4)    /* 9 halo b-rows */
#define SKEYN (SAH * SBH * CW)   /* 14688 words */
#define TCELLS (AT * BT * DGRID) /* 4000 cells per block */
#define NTHREADS 1000
#define QCAP 2048

#define KNF 600000.0f
#define KEYMASK 0xFCFCFCFCu

__device__ unsigned int g_keys[NCELL];

__device__ __forceinline__ int wrapD(int v) {
    if (v < 0) v += DGRID;
    else if (v >= DGRID) v -= DGRID;
    return v;
}

__global__ void __launch_bounds__(512)
key_kernel(const float* __restrict__ xg, const float* __restrict__ yg,
           const float* __restrict__ zg)
{
    int g = blockIdx.x * 512 + threadIdx.x;
    unsigned kx = (unsigned)__float2int_rz(__ldg(xg + g) * 10.0f);
    unsigned ky = (unsigned)__float2int_rz(__ldg(yg + g) * 10.0f);
    unsigned kz = (unsigned)__float2int_rz(__ldg(zg + g) * 10.0f);
    g_keys[g] = kx | (ky << 8) | (kz << 16);
}

__global__ void __launch_bounds__(NTHREADS, 1)
dem_step_kernel(const float* __restrict__ xg, const float* __restrict__ yg,
                const float* __restrict__ zg, const float* __restrict__ vxg,
                const float* __restrict__ vyg, const float* __restrict__ vzg,
                const float* __restrict__ mg, float* __restrict__ out,
                float eta, float dtpm, float gpm)
{
    extern __shared__ char smraw[];
    unsigned int* skey = (unsigned int*)smraw;                 // [SAH][SBH][CW]
    float* fxs = (float*)(skey + SKEYN);                       // [TCELLS]
    float* fys = fxs + TCELLS;
    float* fzs = fys + TCELLS;
    unsigned int* queue = (unsigned int*)(fzs + TCELLS);       // [QCAP]
    unsigned short* lst = (unsigned short*)(queue + QCAP);     // [TCELLS]
    int* cnt  = (int*)(lst + TCELLS);
    int* qcnt = cnt + 1;

    const int tid = threadIdx.x + 200 * threadIdx.y;
    const int b0 = blockIdx.x * BT;
    const int a0 = blockIdx.y * AT;
    const int c  = threadIdx.x;     // 0..199
    const int bl = threadIdx.y;     // 0..4
    const int gb = b0 + bl;

    if (tid == 0) { *cnt = 0; *qcnt = 0; }
    __syncthreads();

    for (int s = tid; s < TCELLS; s += NTHREADS) {
        fxs[s] = 0.f; fys[s] = 0.f; fzs[s] = 0.f;
    }

    // ---- copy precomputed key tile (periodic halo) ----
    for (int s = tid; s < SKEYN; s += NTHREADS) {
        int sc = s % CW; int r = s / CW; int sb = r % SBH; int sa = r / SBH;
        int ga = wrapD(a0 - 2 + sa);
        int gbh = wrapD(b0 - 2 + sb);
        int gc = wrapD(sc - 2);
        skey[s] = __ldg(g_keys + (ga * DGRID + gbh) * DGRID + gc);
    }

    // ---- build compacted list of masked cells (warp-aggregated) ----
    // fixed trip count, all threads active -> ballot is safe here
    {
        const int lane = tid & 31;
        #pragma unroll
        for (int aa = 0; aa < AT; ++aa) {
            const int gp = ((a0 + aa) * DGRID + gb) * DGRID + c;
            bool m = (__ldg(mg + gp) != 0.f);
            unsigned bal = __ballot_sync(0xffffffffu, m);
            if (bal) {
                int base = 0;
                int leader = __ffs(bal) - 1;
                if (lane == leader) base = atomicAdd(cnt, __popc(bal));
                base = __shfl_sync(0xffffffffu, base, leader);
                if (m) {
                    int pos = base + __popc(bal & ((1u << lane) - 1u));
                    lst[pos] = (unsigned short)(aa * 1000 + bl * 200 + c);
                }
            }
        }
    }
    __syncthreads();

    // ---- phase A: screen subtasks = (masked cell, oa); push hits to queue ----
    // NO warp collectives in this variable-trip loop (deadlock hazard).
    {
        const int total = (*cnt) * 5;
        for (int i = tid; i < total; i += NTHREADS) {
            const int j  = i / 5;
            const int oa = i - j * 5;
            const int idx = (int)lst[j];
            const int aa = idx / 1000;
            const int rem = idx - aa * 1000;
            const int pb = rem / 200;
            const int pc = rem - pb * 200;

            const unsigned ck = skey[((aa + 2) * SBH + (pb + 2)) * CW + (pc + 2)];
            const unsigned int* row = skey + (aa + oa) * (SBH * CW) + pb * CW + pc;

            #pragma unroll
            for (int ob = 0; ob < 5; ++ob) {
                unsigned d0 = __vabsdiffu4(row[0], ck) & KEYMASK;
                unsigned d1 = __vabsdiffu4(row[1], ck) & KEYMASK;
                unsigned d2 = __vabsdiffu4(row[2], ck) & KEYMASK;
                unsigned d3 = __vabsdiffu4(row[3], ck) & KEYMASK;
                unsigned d4 = __vabsdiffu4(row[4], ck) & KEYMASK;
                unsigned mn = min(min(d0, d1), min(d2, min(d3, d4)));
                if (mn == 0u) {                  // rare per-lane branch
                    unsigned dd[5] = {d0, d1, d2, d3, d4};
                    #pragma unroll 1
                    for (int oc = 0; oc < 5; ++oc) {
                        if (dd[oc] == 0u) {
                            int pos = atomicAdd(qcnt, 1);
                            if (pos < QCAP)
                                queue[pos] = (unsigned)idx |
                                             ((unsigned)oa << 12) |
                                             ((unsigned)ob << 15) |
                                             ((unsigned)oc << 18);
                        }
                    }
                }
                row += CW;
            }
        }
    }
    __syncthreads();

    // ---- phase B: exact physics on queued candidates ----
    {
        const int qn = min(*qcnt, QCAP);
        for (int t = tid; t < qn; t += NTHREADS) {
            unsigned e = queue[t];
            int idx = (int)(e & 4095u);
            int oa = (int)((e >> 12) & 7u);
            int ob = (int)((e >> 15) & 7u);
            int oc = (int)((e >> 18) & 7u);
            int aa = idx / 1000;
            int rem = idx - aa * 1000;
            int pb = rem / 200;
            int pc = rem - pb * 200;

            int gp = ((a0 + aa) * DGRID + (b0 + pb)) * DGRID + pc;
            int na = wrapD(a0 + aa + oa - 2);
            int nb = wrapD(b0 + pb + ob - 2);
            int nc = wrapD(pc + oc - 2);
            int gq = (na * DGRID + nb) * DGRID + nc;

            float dx = __ldg(xg + gp) - __ldg(xg + gq);
            float dy = __ldg(yg + gp) - __ldg(yg + gq);
            float dz = __ldg(zg + gp) - __ldg(zg + gq);
            float sq = fmaf(dx, dx, fmaf(dy, dy, dz * dz));
            if (sq > 0.f) {
                float dist = sqrtf(sq);
                if (dist < 0.1f) {
                    float dcl = fmaxf(dist, 1e-4f);
                    float dvx = __ldg(vxg + gp) - __ldg(vxg + gq);
                    float dvy = __ldg(vyg + gp) - __ldg(vyg + gq);
                    float dvz = __ldg(vzg + gp) - __ldg(vzg + gq);
                    float vn = (dvx * dx + dvy * dy + dvz * dz) / dcl;
                    float coef = 2.0f * (KNF * (dist - 0.1f) + eta * vn) / dcl;
                    atomicAdd(&fxs[idx], coef * dx);
                    atomicAdd(&fys[idx], coef * dy);
                    atomicAdd(&fzs[idx], coef * dz);
                }
            }
        }
    }
    __syncthreads();

    // ---- update + writeback (all cells) ----
    for (int aa = 0; aa < AT; ++aa) {
        const int gp = ((a0 + aa) * DGRID + gb) * DGRID + c;
        const int idx = aa * 1000 + bl * 200 + c;

        const float xp = __ldg(xg + gp);
        const float yp = __ldg(yg + gp);
        const float zp = __ldg(zg + gp);
        const float vx = __ldg(vxg + gp);
        const float vy = __ldg(vyg + gp);
        const float vz = __ldg(vzg + gp);
        const float m  = __ldg(mg + gp);
        const float fx = fxs[idx], fy = fys[idx], fz = fzs[idx];

        float lft = (xp > 0.1f && xp < 0.15f) ? 1.f : 0.f;
        float rgt = (xp > 9.9f) ? 1.f : 0.f;
        float rtx = ((xp - 10.0f) + 0.05f) + 0.05f;
        float fxb = KNF*lft*(0.15f - xp) - KNF*rgt*rtx - eta*vx*lft - eta*vx*rgt;

        float bot = (yp > 0.1f && yp < 0.15f) ? 1.f : 0.f;
        float top = (yp > 9.9f) ? 1.f : 0.f;
        float rty = ((yp - 10.0f) + 0.05f) + 0.05f;
        float fyb = KNF*bot*(0.15f - yp) - KNF*top*rty - eta*vy*bot - eta*vy*top;

        float fwd = (zp > 0.1f && zp < 0.15f) ? 1.f : 0.f;
        float bck = (zp > 9.9f) ? 1.f : 0.f;
        float rtz = ((zp - 10.0f) + 0.05f) + 0.05f;
        float fzb = KNF*fwd*(0.15f - zp) - KNF*bck*rtz - eta*vz*fwd - eta*vz*bck;

        float vx2 = vx + dtpm * (m * (fxb - fx));
        float vy2 = vy + dtpm * (m * (fyb - fy));
        float vz2 = vz + dtpm * (m * ((gpm - fz) + fzb));
        float x2 = xp + 1e-4f * vx2;
        float y2 = yp + 1e-4f * vy2;
        float z2 = zp + 1e-4f * vz2;

        out[(size_t)0*NCELL + gp] = x2;
        out[(size_t)1*NCELL + gp] = y2;
        out[(size_t)2*NCELL + gp] = z2;
        out[(size_t)3*NCELL + gp] = vx2;
        out[(size_t)4*NCELL + gp] = vy2;
        out[(size_t)5*NCELL + gp] = vz2;
    }
}

extern "C" void kernel_launch(void* const* d_in, const int* in_sizes, int n_in,
                              void* d_out, int out_size)
{
    const float* xg  = (const float*)d_in[0];
    const float* yg  = (const float*)d_in[1];
    const float* zg  = (const float*)d_in[2];
    const float* vxg = (const float*)d_in[3];
    const float* vyg = (const float*)d_in[4];
    const float* vzg = (const float*)d_in[5];
    const float* mg  = (const float*)d_in[6];
    float* out = (float*)d_out;

    const double PMd   = 4.0/3.0 * 3.1415 * 0.05*0.05*0.05 * 2700.0;
    const double alpha = 0.6931471805599453 / 3.141592653589793;
    const double gamm  = alpha / sqrt(alpha*alpha + 1.0);
    const double ETAd  = 2.0 * gamm * sqrt(600000.0 * PMd);
    const float eta  = (float)ETAd;
    const float dtpm = (float)(1e-4 / PMd);
    const float gpm  = (float)(-9.8 * PMd);

    const size_t smem_bytes =
        (size_t)SKEYN * sizeof(unsigned int) +
        (size_t)(3 * TCELLS) * sizeof(float) +
        (size_t)QCAP * sizeof(unsigned int) +
        (size_t)TCELLS * sizeof(unsigned short) +
        32;

    (void)cudaFuncSetAttribute(dem_step_kernel,
                               cudaFuncAttributeMaxDynamicSharedMemorySize,
                               (int)smem_bytes);

    key_kernel<<<NCELL / 512, 512>>>(xg, yg, zg);

    dim3 grid(DGRID / BT, DGRID / AT, 1);   // (40, 50)
    dim3 block(200, BT, 1);                 // 1000 threads
    dem_step_kernel<<<grid, block, smem_bytes>>>(xg, yg, zg, vxg, vyg, vzg, mg,
                                                 out, eta, dtpm, gpm);
}

// round 8
// speedup vs baseline: 1.0233x; 1.0233x over previous
#include <cuda_runtime.h>
#include <math.h>

#define DGRID 200
#define NCELL 8000000
#define AT 4            /* a-layers per block */
#define BT 5            /* b rows per block */
#define CW 204          /* padded row width */
#define SBH 9           /* halo b-rows */
#define PLANE (SBH*CW)  /* 1836 */
#define SKEYN (8*PLANE) /* 14688 words */
#define TCELLS 4000
#define LSTN (TCELLS*5) /* 20000 entries */
#define NTHREADS 1000

#define KNF 600000.0f
#define KEYMASK 0xFCFCFCFCu

__device__ unsigned int g_keys[NCELL];

__device__ __forceinline__ int wrapD(int v) {
    if (v < 0) v += DGRID;
    else if (v >= DGRID) v -= DGRID;
    return v;
}

__global__ void __launch_bounds__(512)
key_kernel(const float* __restrict__ xg, const float* __restrict__ yg,
           const float* __restrict__ zg)
{
    int g = blockIdx.x * 512 + threadIdx.x;
    unsigned kx = (unsigned)__float2int_rz(__ldg(xg + g) * 10.0f);
    unsigned ky = (unsigned)__float2int_rz(__ldg(yg + g) * 10.0f);
    unsigned kz = (unsigned)__float2int_rz(__ldg(zg + g) * 10.0f);
    g_keys[g] = kx | (ky << 8) | (kz << 16);
}

__global__ void __launch_bounds__(NTHREADS, 1)
dem_step_kernel(const float* __restrict__ xg, const float* __restrict__ yg,
                const float* __restrict__ zg, const float* __restrict__ vxg,
                const float* __restrict__ vyg, const float* __restrict__ vzg,
                const float* __restrict__ mg, float* __restrict__ out,
                float eta, float dtpm, float gpm)
{
    extern __shared__ char smraw[];
    unsigned int* skey = (unsigned int*)smraw;                  // [8][9][204]
    float* fall = (float*)(skey + SKEYN);                       // fx|fy|fz [3*4000]
    float* fxs = fall;
    float* fys = fall + TCELLS;
    float* fzs = fall + 2*TCELLS;
    unsigned short* lst = (unsigned short*)(fall + 3*TCELLS);   // [20000]
    int* cnt = (int*)(lst + LSTN);

    const int c  = threadIdx.x;     // 0..199
    const int bl = threadIdx.y;     // 0..4
    const int tid = c + 200 * bl;
    const int b0 = blockIdx.x * BT;
    const int a0 = blockIdx.y * AT;

    if (tid == 0) *cnt = 0;
    #pragma unroll
    for (int s = tid; s < 3*TCELLS; s += NTHREADS) fall[s] = 0.f;

    // ---- halo key copy, division-free ----
    {
        const int gc0 = (c >= 2) ? (c - 2) : (c + 198);          // sc = c
        const int gc1 = (c < 2) ? (198 + c) : (c - 2);           // sc = 200+c (c<4)
        #pragma unroll 1
        for (int sa = 0; sa < 8; ++sa) {
            const int ga = wrapD(a0 - 2 + sa);
            const unsigned* srcp = g_keys + ga * 40000;
            unsigned* dstp = skey + sa * PLANE;
            for (int sb = bl; sb < SBH; sb += BT) {
                const int gbh = wrapD(b0 - 2 + sb);
                const unsigned* src = srcp + gbh * DGRID;
                unsigned* dst = dstp + sb * CW;
                dst[c] = __ldg(src + gc0);
                if (c < 4) dst[200 + c] = __ldg(src + gc1);
            }
        }
    }

    // ---- masked-cell compaction: push 5 packed entries per masked cell ----
    {
        const unsigned amask = __activemask();
        const int lane = tid & 31;
        const unsigned base16 = (unsigned)c | ((unsigned)bl << 8);
        int gp = (a0 * DGRID + (b0 + bl)) * DGRID + c;
        #pragma unroll
        for (int aa = 0; aa < AT; ++aa) {
            bool m = (__ldg(mg + gp) != 0.f);
            unsigned bal = __ballot_sync(amask, m);
            if (bal) {
                int bpos = 0;
                int leader = __ffs(bal) - 1;
                if (lane == leader) bpos = atomicAdd(cnt, __popc(bal));
                bpos = __shfl_sync(amask, bpos, leader);
                if (m) {
                    int pos = (bpos + __popc(bal & ((1u << lane) - 1u))) * 5;
                    unsigned e = base16 | ((unsigned)aa << 11);
                    lst[pos]   = (unsigned short)(e);
                    lst[pos+1] = (unsigned short)(e | (1u << 13));
                    lst[pos+2] = (unsigned short)(e | (2u << 13));
                    lst[pos+3] = (unsigned short)(e | (3u << 13));
                    lst[pos+4] = (unsigned short)(e | (4u << 13));
                }
            }
            gp += 40000;
        }
    }
    __syncthreads();

    // ---- screen + inline exact physics (no collectives: variable-trip loop) ----
    {
        const int total = (*cnt) * 5;
        for (int i = tid; i < total; i += NTHREADS) {
            const unsigned e = (unsigned)lst[i];
            const int pc = (int)(e & 255u);
            const int pb = (int)((e >> 8) & 7u);
            const int aa = (int)((e >> 11) & 3u);
            const int oa = (int)(e >> 13);

            const unsigned ck = skey[(aa*SBH + pb) * CW + pc + 4082];
            const unsigned* row = skey + ((aa + oa) * SBH + pb) * CW + pc;

            #pragma unroll
            for (int ob = 0; ob < 5; ++ob) {
                unsigned d0 = __vabsdiffu4(row[0], ck) & KEYMASK;
                unsigned d1 = __vabsdiffu4(row[1], ck) & KEYMASK;
                unsigned d2 = __vabsdiffu4(row[2], ck) & KEYMASK;
                unsigned d3 = __vabsdiffu4(row[3], ck) & KEYMASK;
                unsigned d4 = __vabsdiffu4(row[4], ck) & KEYMASK;
                unsigned mn = min(min(d0, d1), min(d2, min(d3, d4)));
                if (mn == 0u) {
                    unsigned dd[5] = {d0, d1, d2, d3, d4};
                    const int gp = ((a0 + aa) * DGRID + (b0 + pb)) * DGRID + pc;
                    const float xp = __ldg(xg + gp);
                    const float yp = __ldg(yg + gp);
                    const float zp = __ldg(zg + gp);
                    #pragma unroll 1
                    for (int oc = 0; oc < 5; ++oc) {
                        if (dd[oc] != 0u) continue;
                        int na = wrapD(a0 + aa + oa - 2);
                        int nb = wrapD(b0 + pb + ob - 2);
                        int nc = wrapD(pc + oc - 2);
                        int gq = (na * DGRID + nb) * DGRID + nc;
                        float dx = xp - __ldg(xg + gq);
                        float dy = yp - __ldg(yg + gq);
                        float dz = zp - __ldg(zg + gq);
                        float sq = fmaf(dx, dx, fmaf(dy, dy, dz * dz));
                        if (sq > 0.f) {
                            float dist = sqrtf(sq);
                            if (dist < 0.1f) {
                                float dcl = fmaxf(dist, 1e-4f);
                                float dvx = __ldg(vxg + gp) - __ldg(vxg + gq);
                                float dvy = __ldg(vyg + gp) - __ldg(vyg + gq);
                                float dvz = __ldg(vzg + gp) - __ldg(vzg + gq);
                                float vn = (dvx * dx + dvy * dy + dvz * dz) / dcl;
                                float coef = 2.0f * (KNF * (dist - 0.1f) + eta * vn) / dcl;
                                int cellidx = aa * 1000 + pb * 200 + pc;
                                atomicAdd(&fxs[cellidx], coef * dx);
                                atomicAdd(&fys[cellidx], coef * dy);
                                atomicAdd(&fzs[cellidx], coef * dz);
                            }
                        }
                    }
                }
                row += CW;
            }
        }
    }
    __syncthreads();

    // ---- update + writeback (all cells), incremental indexing ----
    {
        int gp = (a0 * DGRID + (b0 + bl)) * DGRID + c;
        int idx = bl * 200 + c;
        #pragma unroll
        for (int aa = 0; aa < AT; ++aa) {
            const float xp = __ldg(xg + gp);
            const float yp = __ldg(yg + gp);
            const float zp = __ldg(zg + gp);
            const float vx = __ldg(vxg + gp);
            const float vy = __ldg(vyg + gp);
            const float vz = __ldg(vzg + gp);
            const float m  = __ldg(mg + gp);
            const float fx = fxs[idx], fy = fys[idx], fz = fzs[idx];

            float lft = (xp > 0.1f && xp < 0.15f) ? 1.f : 0.f;
            float rgt = (xp > 9.9f) ? 1.f : 0.f;
            float rtx = ((xp - 10.0f) + 0.05f) + 0.05f;
            float fxb = KNF*lft*(0.15f - xp) - KNF*rgt*rtx - eta*vx*lft - eta*vx*rgt;

            float bot = (yp > 0.1f && yp < 0.15f) ? 1.f : 0.f;
            float top = (yp > 9.9f) ? 1.f : 0.f;
            float rty = ((yp - 10.0f) + 0.05f) + 0.05f;
            float fyb = KNF*bot*(0.15f - yp) - KNF*top*rty - eta*vy*bot - eta*vy*top;

            float fwd = (zp > 0.1f && zp < 0.15f) ? 1.f : 0.f;
            float bck = (zp > 9.9f) ? 1.f : 0.f;
            float rtz = ((zp - 10.0f) + 0.05f) + 0.05f;
            float fzb = KNF*fwd*(0.15f - zp) - KNF*bck*rtz - eta*vz*fwd - eta*vz*bck;

            float vx2 = vx + dtpm * (m * (fxb - fx));
            float vy2 = vy + dtpm * (m * (fyb - fy));
            float vz2 = vz + dtpm * (m * ((gpm - fz) + fzb));
            float x2 = xp + 1e-4f * vx2;
            float y2 = yp + 1e-4f * vy2;
            float z2 = zp + 1e-4f * vz2;

            out[(size_t)0*NCELL + gp] = x2;
            out[(size_t)1*NCELL + gp] = y2;
            out[(size_t)2*NCELL + gp] = z2;
            out[(size_t)3*NCELL + gp] = vx2;
            out[(size_t)4*NCELL + gp] = vy2;
            out[(size_t)5*NCELL + gp] = vz2;

            gp += 40000;
            idx += 1000;
        }
    }
}

extern "C" void kernel_launch(void* const* d_in, const int* in_sizes, int n_in,
                              void* d_out, int out_size)
{
    const float* xg  = (const float*)d_in[0];
    const float* yg  = (const float*)d_in[1];
    const float* zg  = (const float*)d_in[2];
    const float* vxg = (const float*)d_in[3];
    const float* vyg = (const float*)d_in[4];
    const float* vzg = (const float*)d_in[5];
    const float* mg  = (const float*)d_in[6];
    float* out = (float*)d_out;

    const double PMd   = 4.0/3.0 * 3.1415 * 0.05*0.05*0.05 * 2700.0;
    const double alpha = 0.6931471805599453 / 3.141592653589793;
    const double gamm  = alpha / sqrt(alpha*alpha + 1.0);
    const double ETAd  = 2.0 * gamm * sqrt(600000.0 * PMd);
    const float eta  = (float)ETAd;
    const float dtpm = (float)(1e-4 / PMd);
    const float gpm  = (float)(-9.8 * PMd);

    const size_t smem_bytes =
        (size_t)SKEYN * sizeof(unsigned int) +
        (size_t)(3 * TCELLS) * sizeof(float) +
        (size_t)LSTN * sizeof(unsigned short) +
        16;

    (void)cudaFuncSetAttribute(dem_step_kernel,
                               cudaFuncAttributeMaxDynamicSharedMemorySize,
                               (int)smem_bytes);

    key_kernel<<<NCELL / 512, 512>>>(xg, yg, zg);

    dim3 grid(DGRID / BT, DGRID / AT, 1);   // (40, 50)
    dim3 block(200, BT, 1);                 // 1000 threads
    dem_step_kernel<<<grid, block, smem_bytes>>>(xg, yg, zg, vxg, vyg, vzg, mg,
                                                 out, eta, dtpm, gpm);
}